// round 11
// baseline (speedup 1.0000x reference)
#include <cuda_runtime.h>
#include <cstdint>

// Problem constants
#define Bsz 16
#define Jn  16
#define Cn  64
#define HW  65536              // 256*256
#define HW4 16384              // float4s per channel
#define NCH (Bsz * Jn)         // 256 channels = 256 CTAs
#define TPB 512
#define BATCH 8                // front-batched float4 loads per iteration
#define NITER (HW4 / (TPB * BATCH))   // 4 iterations

// Device-global scratch (allocation-free; zero-initialized at load)
__device__ float g_joint[NCH];   // per-(b,j) sum of squared errors over C
__device__ int   g_bcnt[Bsz];    // joints completed per batch (reset by electee)

// ---------------------------------------------------------------------------
// Fused kernel: per-(b,j) argmax over heatmap + pred gather + MSE; the 16th
// finisher of each batch immediately writes out[b]  (distributed epilogue).
// ---------------------------------------------------------------------------
__global__ void fused_label_loss(const float* __restrict__ heatmap,
                                 const float* __restrict__ pred,
                                 const float* __restrict__ gt,
                                 float* __restrict__ out)
{
    const int ch  = blockIdx.x;
    const int tid = threadIdx.x;

    const float4* __restrict__ hm =
        reinterpret_cast<const float4*>(heatmap + (size_t)ch * HW);

    float bv  = -3.402823466e+38f;
    int   bfi = tid;                      // winning float4 index

    #pragma unroll
    for (int it = 0; it < NITER; ++it) {
        const int i0 = it * (TPB * BATCH) + tid;

        float4 v[BATCH];
        #pragma unroll
        for (int k = 0; k < BATCH; ++k)   // 8 independent LDG.128, front-batched
            v[k] = hm[i0 + k * TPB];

        #pragma unroll
        for (int k = 0; k < BATCH; ++k) {
            float m01  = fmaxf(v[k].x, v[k].y);
            float m23  = fmaxf(v[k].z, v[k].w);
            float vmax = fmaxf(m01, m23);
            int   fi   = i0 + k * TPB;
            // ascending fi + strict '>' => first occurrence within this thread
            if (vmax > bv) { bv = vmax; bfi = fi; }
        }
    }

    // Recover exact element within winning float4 (re-load; L2 hit).
    // Check descending so the LOWEST matching element index wins.
    float4 wv = hm[bfi];
    int e = 3;
    if (wv.z == bv) e = 2;
    if (wv.y == bv) e = 1;
    if (wv.x == bv) e = 0;
    int bi = bfi * 4 + e;

    // ---- block reduce: larger value wins, lower index on ties ----
    __shared__ float sv[TPB];
    __shared__ int   si[TPB];
    __shared__ float s_warp[2];
    sv[tid] = bv; si[tid] = bi;
    __syncthreads();

    for (int s = TPB / 2; s > 0; s >>= 1) {
        if (tid < s) {
            float ov = sv[tid + s];
            int   oi = si[tid + s];
            if (ov > sv[tid] || (ov == sv[tid] && oi < si[tid])) {
                sv[tid] = ov; si[tid] = oi;
            }
        }
        __syncthreads();
    }

    // ---- fused tail: gather pred @ argmax, squared error over C ----
    const int idx = si[0];
    const int b   = ch >> 4;              // ch / Jn

    if (tid < Cn) {
        float p = pred[((size_t)(b * Cn + tid)) * HW + idx];
        float g = gt[(size_t)ch * Cn + tid];     // (b*Jn+j)*Cn == ch*Cn
        float d = p - g;
        float acc = d * d;
        #pragma unroll
        for (int off = 16; off > 0; off >>= 1)
            acc += __shfl_xor_sync(0xFFFFFFFFu, acc, off);
        if ((tid & 31) == 0) s_warp[tid >> 5] = acc;
    }
    __syncthreads();

    // ---- distributed epilogue: 16th finisher of batch b writes out[b] ----
    if (tid == 0) {
        g_joint[ch] = s_warp[0] + s_warp[1];
        __threadfence();                       // publish g_joint[ch]
        int ob = atomicAdd(&g_bcnt[b], 1);
        if (ob == Jn - 1) {
            g_bcnt[b] = 0;                     // reset for next graph replay
            __threadfence();                   // order counter read -> joint reads
            float tot = 0.f;
            #pragma unroll
            for (int j = 0; j < Jn; ++j)       // fixed order -> deterministic
                tot += __ldcg(&g_joint[b * Jn + j]);
            out[b] = tot * (1.0f / (float)(Jn * Cn));
        }
    }
}

// ---------------------------------------------------------------------------
extern "C" void kernel_launch(void* const* d_in, const int* in_sizes, int n_in,
                              void* d_out, int out_size)
{
    const float* pred    = (const float*)d_in[0];  // [B,C,H,W]
    const float* gt      = (const float*)d_in[1];  // [B,J,C]
    const float* heatmap = (const float*)d_in[2];  // [B,J,H,W]
    float* out = (float*)d_out;                    // [B]

    fused_label_loss<<<NCH, TPB>>>(heatmap, pred, gt, out);
}

// round 12
// speedup vs baseline: 1.0226x; 1.0226x over previous
#include <cuda_runtime.h>
#include <cstdint>

// Problem constants
#define Bsz 16
#define Jn  16
#define Cn  64
#define HW  65536              // 256*256
#define HW4 16384              // float4s per channel
#define NCH (Bsz * Jn)         // 256 channels = 256 CTAs
#define TPB 512
#define BATCH 8                // front-batched float4 loads per iteration
#define NITER (HW4 / (TPB * BATCH))   // 4 iterations

// Device-global scratch (allocation-free; zero-initialized at load)
__device__ float g_joint[NCH];   // per-(b,j) sum of squared errors over C
__device__ int   g_done;         // CTAs completed (reset by the elected CTA)

// ---------------------------------------------------------------------------
// Fused kernel: per-(b,j) argmax over heatmap + pred gather + MSE; the last
// CTA to finish computes the per-batch means and writes out[0..15].
// __launch_bounds__(512, 2): 64-reg budget -> all 8 float4 loads stay in
// flight (serial consume needs no extra arrays, so no spills at the cap).
// ---------------------------------------------------------------------------
__global__ __launch_bounds__(TPB, 2)
void fused_label_loss(const float* __restrict__ heatmap,
                      const float* __restrict__ pred,
                      const float* __restrict__ gt,
                      float* __restrict__ out)
{
    const int ch  = blockIdx.x;
    const int tid = threadIdx.x;

    const float4* __restrict__ hm =
        reinterpret_cast<const float4*>(heatmap + (size_t)ch * HW);

    float bv  = -3.402823466e+38f;
    int   bfi = tid;                      // winning float4 index

    #pragma unroll
    for (int it = 0; it < NITER; ++it) {
        const int i0 = it * (TPB * BATCH) + tid;

        float4 v[BATCH];
        #pragma unroll
        for (int k = 0; k < BATCH; ++k)   // 8 independent LDG.128, front-batched
            v[k] = hm[i0 + k * TPB];

        #pragma unroll
        for (int k = 0; k < BATCH; ++k) {
            float m01  = fmaxf(v[k].x, v[k].y);
            float m23  = fmaxf(v[k].z, v[k].w);
            float vmax = fmaxf(m01, m23);
            int   fi   = i0 + k * TPB;
            // ascending fi + strict '>' => first occurrence within this thread
            if (vmax > bv) { bv = vmax; bfi = fi; }
        }
    }

    // Recover exact element within winning float4 (re-load; L2 hit).
    // Check descending so the LOWEST matching element index wins.
    float4 wv = hm[bfi];
    int e = 3;
    if (wv.z == bv) e = 2;
    if (wv.y == bv) e = 1;
    if (wv.x == bv) e = 0;
    int bi = bfi * 4 + e;

    // ---- block reduce: larger value wins, lower index on ties ----
    __shared__ float sv[TPB];
    __shared__ int   si[TPB];
    __shared__ float s_warp[2];
    sv[tid] = bv; si[tid] = bi;
    __syncthreads();

    for (int s = TPB / 2; s > 0; s >>= 1) {
        if (tid < s) {
            float ov = sv[tid + s];
            int   oi = si[tid + s];
            if (ov > sv[tid] || (ov == sv[tid] && oi < si[tid])) {
                sv[tid] = ov; si[tid] = oi;
            }
        }
        __syncthreads();
    }

    // ---- fused tail: gather pred @ argmax, squared error over C ----
    const int idx = si[0];
    const int b   = ch >> 4;              // ch / Jn

    if (tid < Cn) {
        float p = pred[((size_t)(b * Cn + tid)) * HW + idx];
        float g = gt[(size_t)ch * Cn + tid];     // (b*Jn+j)*Cn == ch*Cn
        float d = p - g;
        float acc = d * d;
        #pragma unroll
        for (int off = 16; off > 0; off >>= 1)
            acc += __shfl_xor_sync(0xFFFFFFFFu, acc, off);
        if ((tid & 31) == 0) s_warp[tid >> 5] = acc;
    }
    __syncthreads();

    // ---- last-done CTA computes the per-batch means ----
    __shared__ int s_last;
    if (tid == 0) {
        g_joint[ch] = s_warp[0] + s_warp[1];
        __threadfence();                   // make g_joint[ch] globally visible
        int old = atomicAdd(&g_done, 1);
        s_last = (old == NCH - 1);
        if (s_last) g_done = 0;            // reset for next graph replay
    }
    __syncthreads();

    if (s_last && tid < Bsz) {
        __threadfence();                   // order: counter read -> g_joint reads
        float tot = 0.f;
        #pragma unroll
        for (int j = 0; j < Jn; ++j)       // fixed order -> deterministic
            tot += *(volatile float*)&g_joint[tid * Jn + j];
        out[tid] = tot * (1.0f / (float)(Jn * Cn));
    }
}

// ---------------------------------------------------------------------------
extern "C" void kernel_launch(void* const* d_in, const int* in_sizes, int n_in,
                              void* d_out, int out_size)
{
    const float* pred    = (const float*)d_in[0];  // [B,C,H,W]
    const float* gt      = (const float*)d_in[1];  // [B,J,C]
    const float* heatmap = (const float*)d_in[2];  // [B,J,H,W]
    float* out = (float*)d_out;                    // [B]

    fused_label_loss<<<NCH, TPB>>>(heatmap, pred, gt, out);
}

// round 13
// speedup vs baseline: 1.0355x; 1.0127x over previous
#include <cuda_runtime.h>
#include <cstdint>

// Problem constants
#define Bsz 16
#define Jn  16
#define Cn  64
#define HW  65536              // 256*256
#define HW4 16384              // float4s per channel
#define NCH (Bsz * Jn)         // 256 channels = 256 CTAs
#define TPB 512
#define NW  (TPB / 32)         // 16 warps
#define BATCH 8                // front-batched float4 loads per iteration
#define NITER (HW4 / (TPB * BATCH))   // 4 iterations

// Device-global scratch (allocation-free; zero-initialized at load)
__device__ float g_joint[NCH];   // per-(b,j) sum of squared errors over C
__device__ int   g_done;         // CTAs completed (reset by the elected CTA)

// (value, index) warp-shuffle combine: larger value wins, lower index on ties
__device__ __forceinline__ void argmax_combine(float& v, int& i, float ov, int oi) {
    if (ov > v || (ov == v && oi < i)) { v = ov; i = oi; }
}

// ---------------------------------------------------------------------------
// Fused kernel: per-(b,j) argmax over heatmap + pred gather + MSE; the last
// CTA to finish computes the per-batch means and writes out[0..15].
// __launch_bounds__(512, 2): 64-reg budget keeps all 8 float4 loads in flight.
// ---------------------------------------------------------------------------
__global__ __launch_bounds__(TPB, 2)
void fused_label_loss(const float* __restrict__ heatmap,
                      const float* __restrict__ pred,
                      const float* __restrict__ gt,
                      float* __restrict__ out)
{
    const int ch   = blockIdx.x;
    const int tid  = threadIdx.x;
    const int lane = tid & 31;
    const int warp = tid >> 5;

    const float4* __restrict__ hm =
        reinterpret_cast<const float4*>(heatmap + (size_t)ch * HW);

    float bv  = -3.402823466e+38f;
    int   bfi = tid;                      // winning float4 index

    #pragma unroll
    for (int it = 0; it < NITER; ++it) {
        const int i0 = it * (TPB * BATCH) + tid;

        float4 v[BATCH];
        #pragma unroll
        for (int k = 0; k < BATCH; ++k)   // 8 independent LDG.128, front-batched
            v[k] = hm[i0 + k * TPB];

        #pragma unroll
        for (int k = 0; k < BATCH; ++k) {
            float m01  = fmaxf(v[k].x, v[k].y);
            float m23  = fmaxf(v[k].z, v[k].w);
            float vmax = fmaxf(m01, m23);
            int   fi   = i0 + k * TPB;
            // ascending fi + strict '>' => first occurrence within this thread
            if (vmax > bv) { bv = vmax; bfi = fi; }
        }
    }

    // Recover exact element within winning float4 (re-load; L2 hit).
    // Check descending so the LOWEST matching element index wins.
    float4 wv = hm[bfi];
    int e = 3;
    if (wv.z == bv) e = 2;
    if (wv.y == bv) e = 1;
    if (wv.x == bv) e = 0;
    int bi = bfi * 4 + e;

    // ---- shuffle-based block argmax reduce (2 barriers total) ----
    __shared__ float s_v[NW];
    __shared__ int   s_i[NW];
    __shared__ int   s_idx;
    __shared__ float s_warp[2];

    #pragma unroll
    for (int off = 16; off > 0; off >>= 1) {
        float ov = __shfl_xor_sync(0xFFFFFFFFu, bv, off);
        int   oi = __shfl_xor_sync(0xFFFFFFFFu, bi, off);
        argmax_combine(bv, bi, ov, oi);
    }
    if (lane == 0) { s_v[warp] = bv; s_i[warp] = bi; }
    __syncthreads();

    if (warp == 0) {
        float v0 = (lane < NW) ? s_v[lane] : -3.402823466e+38f;
        int   i0 = (lane < NW) ? s_i[lane] : 0x7FFFFFFF;
        #pragma unroll
        for (int off = 16; off > 0; off >>= 1) {
            float ov = __shfl_xor_sync(0xFFFFFFFFu, v0, off);
            int   oi = __shfl_xor_sync(0xFFFFFFFFu, i0, off);
            argmax_combine(v0, i0, ov, oi);
        }
        if (lane == 0) s_idx = i0;
    }
    __syncthreads();

    // ---- fused tail: gather pred @ argmax, squared error over C ----
    const int idx = s_idx;
    const int b   = ch >> 4;              // ch / Jn

    if (tid < Cn) {
        float p = pred[((size_t)(b * Cn + tid)) * HW + idx];
        float g = gt[(size_t)ch * Cn + tid];     // (b*Jn+j)*Cn == ch*Cn
        float d = p - g;
        float acc = d * d;
        #pragma unroll
        for (int off = 16; off > 0; off >>= 1)
            acc += __shfl_xor_sync(0xFFFFFFFFu, acc, off);
        if ((tid & 31) == 0) s_warp[tid >> 5] = acc;
    }
    __syncthreads();

    // ---- last-done CTA computes the per-batch means ----
    __shared__ int s_last;
    if (tid == 0) {
        g_joint[ch] = s_warp[0] + s_warp[1];
        __threadfence();                   // make g_joint[ch] globally visible
        int old = atomicAdd(&g_done, 1);
        s_last = (old == NCH - 1);
        if (s_last) g_done = 0;            // reset for next graph replay
    }
    __syncthreads();

    if (s_last && tid < Bsz) {
        __threadfence();                   // order: counter read -> g_joint reads
        float tot = 0.f;
        #pragma unroll
        for (int j = 0; j < Jn; ++j)       // fixed order -> deterministic
            tot += *(volatile float*)&g_joint[tid * Jn + j];
        out[tid] = tot * (1.0f / (float)(Jn * Cn));
    }
}

// ---------------------------------------------------------------------------
extern "C" void kernel_launch(void* const* d_in, const int* in_sizes, int n_in,
                              void* d_out, int out_size)
{
    const float* pred    = (const float*)d_in[0];  // [B,C,H,W]
    const float* gt      = (const float*)d_in[1];  // [B,J,C]
    const float* heatmap = (const float*)d_in[2];  // [B,J,H,W]
    float* out = (float*)d_out;                    // [B]

    fused_label_loss<<<NCH, TPB>>>(heatmap, pred, gt, out);
}

// round 14
// speedup vs baseline: 1.1027x; 1.0649x over previous
#include <cuda_runtime.h>
#include <cstdint>

// Problem constants
#define Bsz 16
#define Jn  16
#define Cn  64
#define HW  65536              // 256*256
#define HW4 16384              // float4s per channel
#define NCH (Bsz * Jn)         // 256 channels = 256 CTAs
#define TPB 512
#define NW  (TPB / 32)         // 16 warps
#define BATCH 8                // front-batched float4 loads per iteration
#define NITER (HW4 / (TPB * BATCH))   // 4 iterations

// Device-global scratch (allocation-free; zero-initialized at load)
__device__ float g_joint[NCH];   // per-(b,j) sum of squared errors over C
__device__ int   g_done;         // CTAs completed (reset by the elected CTA)

// (value, float4-index) combine: larger value wins, lower index on ties.
// Valid at float4 granularity: all elements of float4 i precede those of i+1.
__device__ __forceinline__ void argmax_combine(float& v, int& i, float ov, int oi) {
    if (ov > v || (ov == v && oi < i)) { v = ov; i = oi; }
}

// ---------------------------------------------------------------------------
// Fused kernel: per-(b,j) argmax over heatmap + pred gather + MSE; the last
// CTA to finish computes the per-batch means and writes out[0..15].
// __launch_bounds__(512, 2): 64-reg budget keeps all 8 float4 loads in flight.
// ---------------------------------------------------------------------------
__global__ __launch_bounds__(TPB, 2)
void fused_label_loss(const float* __restrict__ heatmap,
                      const float* __restrict__ pred,
                      const float* __restrict__ gt,
                      float* __restrict__ out)
{
    const int ch   = blockIdx.x;
    const int tid  = threadIdx.x;
    const int lane = tid & 31;
    const int warp = tid >> 5;

    const float4* __restrict__ hm =
        reinterpret_cast<const float4*>(heatmap + (size_t)ch * HW);

    float bv  = -3.402823466e+38f;
    int   bfi = tid;                      // winning float4 index

    #pragma unroll
    for (int it = 0; it < NITER; ++it) {
        const int i0 = it * (TPB * BATCH) + tid;

        float4 v[BATCH];
        #pragma unroll
        for (int k = 0; k < BATCH; ++k)   // 8 independent LDG.128, front-batched
            v[k] = hm[i0 + k * TPB];

        #pragma unroll
        for (int k = 0; k < BATCH; ++k) {
            float m01  = fmaxf(v[k].x, v[k].y);
            float m23  = fmaxf(v[k].z, v[k].w);
            float vmax = fmaxf(m01, m23);
            int   fi   = i0 + k * TPB;
            // ascending fi + strict '>' => first occurrence within this thread
            if (vmax > bv) { bv = vmax; bfi = fi; }
        }
    }

    // ---- block argmax reduce on (value, float4 index); 1 barrier ----
    __shared__ float s_v[NW];
    __shared__ int   s_i[NW];
    __shared__ float s_warp[2];

    #pragma unroll
    for (int off = 16; off > 0; off >>= 1) {
        float ov = __shfl_xor_sync(0xFFFFFFFFu, bv, off);
        int   oi = __shfl_xor_sync(0xFFFFFFFFu, bfi, off);
        argmax_combine(bv, bfi, ov, oi);
    }
    if (lane == 0) { s_v[warp] = bv; s_i[warp] = bfi; }
    __syncthreads();

    // ---- warps 0 & 1 redundantly finish the reduce (butterfly -> every lane
    //      holds the winner), recover the element, and gather — no 2nd barrier
    const int b = ch >> 4;                // ch / Jn
    if (warp < 2) {
        float v0 = (lane < NW) ? s_v[lane] : -3.402823466e+38f;
        int   i0 = (lane < NW) ? s_i[lane] : 0x7FFFFFFF;
        #pragma unroll
        for (int off = 16; off > 0; off >>= 1) {
            float ov = __shfl_xor_sync(0xFFFFFFFFu, v0, off);
            int   oi = __shfl_xor_sync(0xFFFFFFFFu, i0, off);
            argmax_combine(v0, i0, ov, oi);
        }

        // Recover exact element within winning float4 (broadcast reload, L1/L2
        // hit). Descending checks so the LOWEST matching element index wins.
        float4 wv = hm[i0];
        int e = 3;
        if (wv.z == v0) e = 2;
        if (wv.y == v0) e = 1;
        if (wv.x == v0) e = 0;
        const int idx = i0 * 4 + e;

        // ---- fused tail: gather pred @ argmax, squared error over C ----
        float p = pred[((size_t)(b * Cn + tid)) * HW + idx];
        float g = gt[(size_t)ch * Cn + tid];     // (b*Jn+j)*Cn == ch*Cn
        float d = p - g;
        float acc = d * d;
        #pragma unroll
        for (int off = 16; off > 0; off >>= 1)
            acc += __shfl_xor_sync(0xFFFFFFFFu, acc, off);
        if (lane == 0) s_warp[warp] = acc;
    }
    __syncthreads();

    // ---- last-done CTA computes the per-batch means ----
    __shared__ int s_last;
    if (tid == 0) {
        g_joint[ch] = s_warp[0] + s_warp[1];
        __threadfence();                   // make g_joint[ch] globally visible
        int old = atomicAdd(&g_done, 1);
        s_last = (old == NCH - 1);
        if (s_last) g_done = 0;            // reset for next graph replay
    }
    __syncthreads();

    if (s_last && tid < Bsz) {
        __threadfence();                   // order: counter read -> g_joint reads
        float tot = 0.f;
        #pragma unroll
        for (int j = 0; j < Jn; ++j)       // fixed order -> deterministic
            tot += *(volatile float*)&g_joint[tid * Jn + j];
        out[tid] = tot * (1.0f / (float)(Jn * Cn));
    }
}

// ---------------------------------------------------------------------------
extern "C" void kernel_launch(void* const* d_in, const int* in_sizes, int n_in,
                              void* d_out, int out_size)
{
    const float* pred    = (const float*)d_in[0];  // [B,C,H,W]
    const float* gt      = (const float*)d_in[1];  // [B,J,C]
    const float* heatmap = (const float*)d_in[2];  // [B,J,H,W]
    float* out = (float*)d_out;                    // [B]

    fused_label_loss<<<NCH, TPB>>>(heatmap, pred, gt, out);
}

// round 16
// speedup vs baseline: 1.2179x; 1.1045x over previous
#include <cuda_runtime.h>
#include <cstdint>

// Problem constants
#define Bsz 16
#define Jn  16
#define Cn  64
#define HW  65536              // 256*256
#define HW4 16384              // float4s per channel
#define NCH (Bsz * Jn)         // 256 channels = 256 CTAs
#define TPB 512
#define NW  (TPB / 32)         // 16 warps
#define BATCH 8                // front-batched float4 loads per iteration
#define NITER (HW4 / (TPB * BATCH))   // 4 iterations

// Device-global scratch (allocation-free; zero-initialized at load)
__device__ float g_joint[NCH];   // per-(b,j) sum of squared errors over C
__device__ int   g_done;         // CTAs completed (reset by the elected CTA)

// (value, float4-index) combine: larger value wins, lower index on ties.
// Valid at float4 granularity: all elements of float4 i precede those of i+1.
__device__ __forceinline__ void argmax_combine(float& v, int& i, float ov, int oi) {
    if (ov > v || (ov == v && oi < i)) { v = ov; i = oi; }
}

// ---------------------------------------------------------------------------
// Fused kernel: per-(b,j) argmax over heatmap + pred gather + MSE; the last
// CTA to finish computes the per-batch means and writes out[0..15].
// __launch_bounds__(512, 2): 64-reg budget keeps all 8 float4 loads in flight.
// Heatmap streamed with __ldcg (L2-only): zero L1 reuse, skip L1 fills.
// ---------------------------------------------------------------------------
__global__ __launch_bounds__(TPB, 2)
void fused_label_loss(const float* __restrict__ heatmap,
                      const float* __restrict__ pred,
                      const float* __restrict__ gt,
                      float* __restrict__ out)
{
    const int ch   = blockIdx.x;
    const int tid  = threadIdx.x;
    const int lane = tid & 31;
    const int warp = tid >> 5;

    const float4* __restrict__ hm =
        reinterpret_cast<const float4*>(heatmap + (size_t)ch * HW);

    float bv  = -3.402823466e+38f;
    int   bfi = tid;                      // winning float4 index

    #pragma unroll
    for (int it = 0; it < NITER; ++it) {
        const int i0 = it * (TPB * BATCH) + tid;

        float4 v[BATCH];
        #pragma unroll
        for (int k = 0; k < BATCH; ++k)   // 8 independent LDG.128, L2-only
            v[k] = __ldcg(&hm[i0 + k * TPB]);

        #pragma unroll
        for (int k = 0; k < BATCH; ++k) {
            float m01  = fmaxf(v[k].x, v[k].y);
            float m23  = fmaxf(v[k].z, v[k].w);
            float vmax = fmaxf(m01, m23);
            int   fi   = i0 + k * TPB;
            // ascending fi + strict '>' => first occurrence within this thread
            if (vmax > bv) { bv = vmax; bfi = fi; }
        }
    }

    // ---- block argmax reduce on (value, float4 index); 1 barrier ----
    __shared__ float s_v[NW];
    __shared__ int   s_i[NW];
    __shared__ float s_warp[2];

    #pragma unroll
    for (int off = 16; off > 0; off >>= 1) {
        float ov = __shfl_xor_sync(0xFFFFFFFFu, bv, off);
        int   oi = __shfl_xor_sync(0xFFFFFFFFu, bfi, off);
        argmax_combine(bv, bfi, ov, oi);
    }
    if (lane == 0) { s_v[warp] = bv; s_i[warp] = bfi; }
    __syncthreads();

    // ---- warps 0 & 1 redundantly finish the reduce (butterfly -> every lane
    //      holds the winner), recover the element, and gather — no 2nd barrier
    const int b = ch >> 4;                // ch / Jn
    if (warp < 2) {
        float v0 = (lane < NW) ? s_v[lane] : -3.402823466e+38f;
        int   i0 = (lane < NW) ? s_i[lane] : 0x7FFFFFFF;
        #pragma unroll
        for (int off = 16; off > 0; off >>= 1) {
            float ov = __shfl_xor_sync(0xFFFFFFFFu, v0, off);
            int   oi = __shfl_xor_sync(0xFFFFFFFFu, i0, off);
            argmax_combine(v0, i0, ov, oi);
        }

        // Recover exact element within winning float4 (broadcast reload, L2
        // hit). Descending checks so the LOWEST matching element index wins.
        float4 wv = __ldcg(&hm[i0]);
        int e = 3;
        if (wv.z == v0) e = 2;
        if (wv.y == v0) e = 1;
        if (wv.x == v0) e = 0;
        const int idx = i0 * 4 + e;

        // ---- fused tail: gather pred @ argmax, squared error over C ----
        float p = pred[((size_t)(b * Cn + tid)) * HW + idx];
        float g = gt[(size_t)ch * Cn + tid];     // (b*Jn+j)*Cn == ch*Cn
        float d = p - g;
        float acc = d * d;
        #pragma unroll
        for (int off = 16; off > 0; off >>= 1)
            acc += __shfl_xor_sync(0xFFFFFFFFu, acc, off);
        if (lane == 0) s_warp[warp] = acc;
    }
    __syncthreads();

    // ---- last-done CTA computes the per-batch means ----
    __shared__ int s_last;
    if (tid == 0) {
        g_joint[ch] = s_warp[0] + s_warp[1];
        __threadfence();                   // make g_joint[ch] globally visible
        int old = atomicAdd(&g_done, 1);
        s_last = (old == NCH - 1);
        if (s_last) g_done = 0;            // reset for next graph replay
    }
    __syncthreads();

    if (s_last && tid < Bsz) {
        __threadfence();                   // order: counter read -> g_joint reads
        float tot = 0.f;
        #pragma unroll
        for (int j = 0; j < Jn; ++j)       // fixed order -> deterministic
            tot += *(volatile float*)&g_joint[tid * Jn + j];
        out[tid] = tot * (1.0f / (float)(Jn * Cn));
    }
}

// ---------------------------------------------------------------------------
extern "C" void kernel_launch(void* const* d_in, const int* in_sizes, int n_in,
                              void* d_out, int out_size)
{
    const float* pred    = (const float*)d_in[0];  // [B,C,H,W]
    const float* gt      = (const float*)d_in[1];  // [B,J,C]
    const float* heatmap = (const float*)d_in[2];  // [B,J,H,W]
    float* out = (float*)d_out;                    // [B]

    fused_label_loss<<<NCH, TPB>>>(heatmap, pred, gt, out);
}